// round 1
// baseline (speedup 1.0000x reference)
#include <cuda_runtime.h>
#include <math.h>

#define NNODES 81920
#define NEDGES 1310720
#define NG     4096
#define NPG    20
#define IND    128
#define D      256
#define HIDC   64
#define NH     4
#define MAXE   1044   // per-graph edge cap incl. 20 self loops (mean 340, 39-sigma safe)

// ---------------- scratch (no allocations allowed) ----------------
__device__ __align__(16) float g_h1lin[NNODES * D];
__device__ __align__(16) float g_h1   [NNODES * D];
__device__ __align__(16) float g_h2lin[NNODES * D];
__device__ int g_cnt[NG];
__device__ int g_off[NG + 1];
__device__ int g_cur[NG];
__device__ unsigned short g_epack[NEDGES];

// ---------------- edge preprocessing ----------------
__global__ void k_zero() {
    int i = blockIdx.x * blockDim.x + threadIdx.x;
    if (i < NG) g_cnt[i] = 0;
}

__global__ void k_hist(const int* __restrict__ ei) {
    int e = blockIdx.x * blockDim.x + threadIdx.x;
    if (e < NEDGES) {
        int dst = ei[NEDGES + e];
        atomicAdd(&g_cnt[dst / NPG], 1);
    }
}

__global__ void k_scan() {
    __shared__ int s[NG];
    int t = threadIdx.x;  // 1024 threads
    for (int i = t; i < NG; i += 1024) s[i] = g_cnt[i];
    __syncthreads();
    for (int off = 1; off < NG; off <<= 1) {
        int v[4];
        #pragma unroll
        for (int j = 0; j < 4; j++) {
            int i = t + j * 1024;
            v[j] = (i >= off) ? s[i - off] : 0;
        }
        __syncthreads();
        #pragma unroll
        for (int j = 0; j < 4; j++) {
            int i = t + j * 1024;
            s[i] += v[j];
        }
        __syncthreads();
    }
    for (int i = t; i < NG; i += 1024) {
        g_off[i + 1] = s[i];
        g_cur[i] = s[i] - g_cnt[i];  // exclusive
    }
    if (t == 0) g_off[0] = 0;
}

__global__ void k_scatter(const int* __restrict__ ei) {
    int e = blockIdx.x * blockDim.x + threadIdx.x;
    if (e < NEDGES) {
        int s = ei[e];
        int d = ei[NEDGES + e];
        int g = d / NPG;
        int p = atomicAdd(&g_cur[g], 1);
        g_epack[p] = (unsigned short)(((s - g * NPG) << 5) | (d - g * NPG));
    }
}

// ---------------- fp32 NT GEMM: C[M,256] = A[M,K] * W[256,K]^T ----------------
// BM=128, BN=128, BK=16, 256 threads, 8x8 microtile
template <int K>
__global__ __launch_bounds__(256)
void k_gemm(const float* __restrict__ A, const float* __restrict__ W,
            float* __restrict__ C) {
    __shared__ float Ash[16][132];
    __shared__ float Bsh[16][132];
    const int m0 = blockIdx.x * 128;
    const int n0 = blockIdx.y * 128;
    const int tid = threadIdx.x;
    const int tx = tid & 15, ty = tid >> 4;

    float acc[8][8];
    #pragma unroll
    for (int i = 0; i < 8; i++)
        #pragma unroll
        for (int j = 0; j < 8; j++) acc[i][j] = 0.f;

    for (int kk = 0; kk < K; kk += 16) {
        #pragma unroll
        for (int l = 0; l < 2; l++) {
            int f = tid + l * 256;
            int row = f >> 2, quad = f & 3;
            float4 va = *(const float4*)&A[(size_t)(m0 + row) * K + kk + quad * 4];
            Ash[quad * 4 + 0][row] = va.x;
            Ash[quad * 4 + 1][row] = va.y;
            Ash[quad * 4 + 2][row] = va.z;
            Ash[quad * 4 + 3][row] = va.w;
            float4 vb = *(const float4*)&W[(size_t)(n0 + row) * K + kk + quad * 4];
            Bsh[quad * 4 + 0][row] = vb.x;
            Bsh[quad * 4 + 1][row] = vb.y;
            Bsh[quad * 4 + 2][row] = vb.z;
            Bsh[quad * 4 + 3][row] = vb.w;
        }
        __syncthreads();
        #pragma unroll
        for (int k = 0; k < 16; k++) {
            float4 a0 = *(float4*)&Ash[k][ty * 4];
            float4 a1 = *(float4*)&Ash[k][ty * 4 + 64];
            float4 b0 = *(float4*)&Bsh[k][tx * 4];
            float4 b1 = *(float4*)&Bsh[k][tx * 4 + 64];
            float am[8] = {a0.x, a0.y, a0.z, a0.w, a1.x, a1.y, a1.z, a1.w};
            float bm[8] = {b0.x, b0.y, b0.z, b0.w, b1.x, b1.y, b1.z, b1.w};
            #pragma unroll
            for (int i = 0; i < 8; i++)
                #pragma unroll
                for (int j = 0; j < 8; j++) acc[i][j] += am[i] * bm[j];
        }
        __syncthreads();
    }
    #pragma unroll
    for (int i = 0; i < 8; i++) {
        int r = m0 + ((i < 4) ? (ty * 4 + i) : (64 + ty * 4 + i - 4));
        float4 v0 = make_float4(acc[i][0], acc[i][1], acc[i][2], acc[i][3]);
        float4 v1 = make_float4(acc[i][4], acc[i][5], acc[i][6], acc[i][7]);
        *(float4*)&C[(size_t)r * D + n0 + tx * 4] = v0;
        *(float4*)&C[(size_t)r * D + n0 + 64 + tx * 4] = v1;
    }
}

// ---------------- layer-1 attention: full per-graph GAT softmax+agg+bias+ELU ----------------
__global__ __launch_bounds__(256)
void k_attn1(const float* __restrict__ asrc, const float* __restrict__ adst,
             const float* __restrict__ bias) {
    __shared__ float hsh[NPG][D];
    __shared__ float ssrc[NPG][NH], sdst[NPG][NH];
    __shared__ float ash[NH * HIDC], adsh[NH * HIDC];
    __shared__ float bsh[D];
    __shared__ unsigned short esh[MAXE];
    __shared__ unsigned short srcs[MAXE];
    __shared__ float alpha[MAXE * NH];
    __shared__ int deg[NPG], dstart[NPG + 1], dcur[NPG];
    __shared__ int s_nE;

    const int g = blockIdx.x;
    const int tid = threadIdx.x;
    const int base = g * NPG;

    const float* hp = g_h1lin + (size_t)base * D;
    for (int i = tid; i < NPG * D / 4; i += 256)
        ((float4*)&hsh[0][0])[i] = ((const float4*)hp)[i];
    for (int i = tid; i < NH * HIDC; i += 256) { ash[i] = asrc[i]; adsh[i] = adst[i]; }
    for (int i = tid; i < D; i += 256) bsh[i] = bias[i];
    if (tid < NPG) deg[tid] = 0;

    int off = g_off[g];
    int cnt = g_off[g + 1] - off;
    if (cnt > MAXE - NPG) cnt = MAXE - NPG;
    for (int j = tid; j < cnt; j += 256) esh[j] = g_epack[off + j];
    if (tid < NPG) esh[cnt + tid] = (unsigned short)((tid << 5) | tid);  // self loops
    if (tid == 0) s_nE = cnt + NPG;
    __syncthreads();
    const int nE = s_nE;

    // per-node attention scores s_src, s_dst
    if (tid < 2 * NPG * NH) {
        int t = tid;
        int which = t >= NPG * NH;
        t -= which * NPG * NH;
        int i = t / NH, h = t % NH;
        const float* av = which ? &adsh[h * HIDC] : &ash[h * HIDC];
        float s = 0.f;
        #pragma unroll 8
        for (int c = 0; c < HIDC; c++) s += hsh[i][h * HIDC + c] * av[c];
        if (which) sdst[i][h] = s; else ssrc[i][h] = s;
    }
    // per-dst degree histogram
    for (int j = tid; j < nE; j += 256) atomicAdd(&deg[esh[j] & 31], 1);
    __syncthreads();
    if (tid == 0) {
        int a = 0;
        for (int i = 0; i < NPG; i++) { dstart[i] = a; dcur[i] = a; a += deg[i]; }
        dstart[NPG] = a;
    }
    __syncthreads();
    for (int j = tid; j < nE; j += 256) {
        unsigned short ev = esh[j];
        int dl = ev & 31;
        int p = atomicAdd(&dcur[dl], 1);
        srcs[p] = ev >> 5;
    }
    __syncthreads();
    // segment softmax per (dst, head)
    if (tid < NPG * NH) {
        int dI = tid / NH, h = tid % NH;
        int p0 = dstart[dI], p1 = dstart[dI + 1];
        float sd = sdst[dI][h];
        float mx = -1e30f;
        for (int p = p0; p < p1; p++) {
            float v = ssrc[srcs[p]][h] + sd;
            v = (v >= 0.f) ? v : 0.2f * v;
            alpha[p * NH + h] = v;
            mx = fmaxf(mx, v);
        }
        float sum = 0.f;
        for (int p = p0; p < p1; p++) {
            float ex = expf(alpha[p * NH + h] - mx);
            alpha[p * NH + h] = ex;
            sum += ex;
        }
        float r = 1.f / (sum + 1e-16f);
        for (int p = p0; p < p1; p++) alpha[p * NH + h] *= r;
    }
    __syncthreads();
    // aggregate: one thread per output channel
    const int c = tid;
    const int h = c >> 6;
    float* outp = g_h1 + (size_t)base * D;
    for (int dI = 0; dI < NPG; dI++) {
        int p0 = dstart[dI], p1 = dstart[dI + 1];
        float acc = 0.f;
        for (int p = p0; p < p1; p++)
            acc += alpha[p * NH + h] * hsh[srcs[p]][c];
        float v = acc + bsh[c];
        v = (v > 0.f) ? v : expm1f(v);
        outp[dI * D + c] = v;
    }
}

// ---------------- layer-2 attention at super node (dst=19) + MLP head ----------------
__global__ __launch_bounds__(256)
void k_attn2(const float* __restrict__ asrc, const float* __restrict__ adst,
             const float* __restrict__ bias2,
             const float* __restrict__ Wh, const float* __restrict__ bh,
             const float* __restrict__ Wc, const float* __restrict__ bc,
             float* __restrict__ out) {
    __shared__ float hsh[NPG][D];
    __shared__ float ssrc[NPG][NH];
    __shared__ float sd19[NH];
    __shared__ float ash[NH * HIDC], adsh[NH * HIDC];
    __shared__ float b2sh[D];
    __shared__ unsigned short l19[192];
    __shared__ int s_n19;
    __shared__ float al19[192 * NH];
    __shared__ float xs[D];
    __shared__ float hcls[HIDC];

    const int g = blockIdx.x;
    const int tid = threadIdx.x;
    const int base = g * NPG;

    const float* hp = g_h2lin + (size_t)base * D;
    for (int i = tid; i < NPG * D / 4; i += 256)
        ((float4*)&hsh[0][0])[i] = ((const float4*)hp)[i];
    for (int i = tid; i < NH * HIDC; i += 256) { ash[i] = asrc[i]; adsh[i] = adst[i]; }
    for (int i = tid; i < D; i += 256) b2sh[i] = bias2[i];
    if (tid == 0) s_n19 = 0;
    __syncthreads();

    int off = g_off[g], cnt = g_off[g + 1] - off;
    for (int j = tid; j < cnt; j += 256) {
        unsigned short ev = g_epack[off + j];
        if ((ev & 31) == 19) {
            int p = atomicAdd(&s_n19, 1);
            if (p < 191) l19[p] = ev >> 5;
        }
    }
    if (tid < NPG * NH) {
        int i = tid / NH, h = tid % NH;
        float s = 0.f;
        #pragma unroll 8
        for (int c = 0; c < HIDC; c++) s += hsh[i][h * HIDC + c] * ash[h * HIDC + c];
        ssrc[i][h] = s;
    } else if (tid < NPG * NH + NH) {
        int h = tid - NPG * NH;
        float s = 0.f;
        #pragma unroll 8
        for (int c = 0; c < HIDC; c++) s += hsh[19][h * HIDC + c] * adsh[h * HIDC + c];
        sd19[h] = s;
    }
    __syncthreads();
    if (tid == 0) {  // append self loop (19,19)
        int m = s_n19 < 191 ? s_n19 : 191;
        l19[m] = 19;
        s_n19 = m + 1;
    }
    __syncthreads();
    const int ne = s_n19;

    if (tid < NH) {
        int h = tid;
        float sd = sd19[h];
        float mx = -1e30f;
        for (int p = 0; p < ne; p++) {
            float v = ssrc[l19[p]][h] + sd;
            v = (v >= 0.f) ? v : 0.2f * v;
            al19[p * NH + h] = v;
            mx = fmaxf(mx, v);
        }
        float sum = 0.f;
        for (int p = 0; p < ne; p++) {
            float ex = expf(al19[p * NH + h] - mx);
            al19[p * NH + h] = ex;
            sum += ex;
        }
        float r = 1.f / (sum + 1e-16f);
        for (int p = 0; p < ne; p++) al19[p * NH + h] *= r;
    }
    __syncthreads();
    {   // xs[c] = elu(agg + b2)
        int c = tid, h = c >> 6;
        float acc = 0.f;
        for (int p = 0; p < ne; p++)
            acc += al19[p * NH + h] * hsh[l19[p]][c];
        float v = acc + b2sh[c];
        xs[c] = (v > 0.f) ? v : expm1f(v);
    }
    __syncthreads();
    // hidden layer: warp w computes j = w*8 .. w*8+7, lanes parallel over k
    const int w = tid >> 5, lane = tid & 31;
    #pragma unroll
    for (int jj = 0; jj < 8; jj++) {
        int j = w * 8 + jj;
        float a = 0.f;
        for (int k = lane; k < D; k += 32) a += xs[k] * Wh[j * D + k];
        #pragma unroll
        for (int o = 16; o; o >>= 1) a += __shfl_xor_sync(0xffffffffu, a, o);
        if (lane == 0) {
            float v = a + bh[j];
            hcls[j] = (v > 0.f) ? v : 0.f;
        }
    }
    __syncthreads();
    if (tid < 32) {
        float a = hcls[tid] * Wc[tid] + hcls[tid + 32] * Wc[tid + 32];
        #pragma unroll
        for (int o = 16; o; o >>= 1) a += __shfl_xor_sync(0xffffffffu, a, o);
        if (tid == 0) out[g] = a + bc[0];
    }
}

// ---------------- launcher ----------------
extern "C" void kernel_launch(void* const* d_in, const int* in_sizes, int n_in,
                              void* d_out, int out_size) {
    const float* x   = (const float*)d_in[0];
    const int*   ei  = (const int*)d_in[1];
    // d_in[2] = batch (unused; graph id derivable as node/20)
    const float* W1  = (const float*)d_in[3];
    const float* a1s = (const float*)d_in[4];
    const float* a1d = (const float*)d_in[5];
    const float* b1  = (const float*)d_in[6];
    const float* W2  = (const float*)d_in[7];
    const float* a2s = (const float*)d_in[8];
    const float* a2d = (const float*)d_in[9];
    const float* b2  = (const float*)d_in[10];
    const float* Wh  = (const float*)d_in[11];
    const float* bh  = (const float*)d_in[12];
    const float* Wc  = (const float*)d_in[13];
    const float* bc  = (const float*)d_in[14];
    float* out = (float*)d_out;

    void *p_h1lin, *p_h1, *p_h2lin;
    cudaGetSymbolAddress(&p_h1lin, g_h1lin);
    cudaGetSymbolAddress(&p_h1, g_h1);
    cudaGetSymbolAddress(&p_h2lin, g_h2lin);

    k_zero<<<(NG + 255) / 256, 256>>>();
    k_hist<<<(NEDGES + 255) / 256, 256>>>(ei);
    k_scan<<<1, 1024>>>();
    k_scatter<<<(NEDGES + 255) / 256, 256>>>(ei);

    k_gemm<IND><<<dim3(NNODES / 128, D / 128), 256>>>(x, W1, (float*)p_h1lin);
    k_attn1<<<NG, 256>>>(a1s, a1d, b1);
    k_gemm<D><<<dim3(NNODES / 128, D / 128), 256>>>((const float*)p_h1, W2, (float*)p_h2lin);
    k_attn2<<<NG, 256>>>(a2s, a2d, b2, Wh, bh, Wc, bc, out);
}

// round 3
// speedup vs baseline: 1.3888x; 1.3888x over previous
#include <cuda_runtime.h>
#include <cuda_bf16.h>
#include <math.h>
#include <stdint.h>

#define NNODES 81920
#define NEDGES 1310720
#define NG     4096
#define NPG    20
#define IND    128
#define D      256
#define HIDC   64
#define NH     4
#define CAP    512            // per-graph edge capacity (mean 320, +10.7 sigma)
#define MAXE   (CAP + NPG)    // incl. self loops

// ---------------- scratch (no allocations allowed) ----------------
__device__ __align__(16) float g_h1lin[NNODES * D];
__device__ __align__(16) float g_h2lin[NNODES * D];
__device__ __align__(16) __nv_bfloat16 g_xhi[NNODES * IND];
__device__ __align__(16) __nv_bfloat16 g_xlo[NNODES * IND];
__device__ __align__(16) __nv_bfloat16 g_h1hi[NNODES * D];
__device__ __align__(16) __nv_bfloat16 g_h1lo[NNODES * D];
__device__ __align__(16) __nv_bfloat16 g_w1hi[D * IND];
__device__ __align__(16) __nv_bfloat16 g_w1lo[D * IND];
__device__ __align__(16) __nv_bfloat16 g_w2hi[D * D];
__device__ __align__(16) __nv_bfloat16 g_w2lo[D * D];
__device__ int g_cur[NG];
__device__ unsigned short g_epack[NG * CAP];

// ================= helpers =================
__device__ __forceinline__ uint32_t cvta_smem(const void* p) {
    uint32_t a;
    asm("{ .reg .u64 t; cvta.to.shared.u64 t, %1; cvt.u32.u64 %0, t; }" : "=r"(a) : "l"(p));
    return a;
}
__device__ __forceinline__ void cp16(uint32_t dst, const void* src) {
    asm volatile("cp.async.cg.shared.global [%0], [%1], 16;" :: "r"(dst), "l"(src) : "memory");
}
__device__ __forceinline__ void mma_bf16(float* d, const uint32_t* a, uint32_t b0, uint32_t b1) {
    asm volatile(
        "mma.sync.aligned.m16n8k16.row.col.f32.bf16.bf16.f32 "
        "{%0,%1,%2,%3}, {%4,%5,%6,%7}, {%8,%9}, {%0,%1,%2,%3};"
        : "+f"(d[0]), "+f"(d[1]), "+f"(d[2]), "+f"(d[3])
        : "r"(a[0]), "r"(a[1]), "r"(a[2]), "r"(a[3]), "r"(b0), "r"(b1));
}

// ---------------- edge preprocessing ----------------
__global__ void k_zero() {
    int i = blockIdx.x * blockDim.x + threadIdx.x;
    if (i < NG) g_cur[i] = 0;
}

__global__ void k_scatter(const int* __restrict__ ei) {
    int e = blockIdx.x * blockDim.x + threadIdx.x;
    if (e < NEDGES) {
        int s = ei[e];
        int d = ei[NEDGES + e];
        int g = d / NPG;
        int p = atomicAdd(&g_cur[g], 1);
        if (p < CAP)
            g_epack[g * CAP + p] = (unsigned short)(((s - g * NPG) << 5) | (d - g * NPG));
    }
}

// ---------------- fp32 -> bf16 hi/lo split ----------------
__global__ void k_split(const float* __restrict__ src, __nv_bfloat16* __restrict__ hi,
                        __nv_bfloat16* __restrict__ lo, int n4) {
    int i = blockIdx.x * blockDim.x + threadIdx.x;
    if (i < n4) {
        float4 v = ((const float4*)src)[i];
        __nv_bfloat16 h[4], l[4];
        float vv[4] = {v.x, v.y, v.z, v.w};
        #pragma unroll
        for (int j = 0; j < 4; j++) {
            h[j] = __float2bfloat16(vv[j]);
            l[j] = __float2bfloat16(vv[j] - __bfloat162float(h[j]));
        }
        ((uint2*)hi)[i] = *(uint2*)h;
        ((uint2*)lo)[i] = *(uint2*)l;
    }
}

// ============ bf16x3 mma.sync GEMM: C[M,256] = A[M,K] * W[256,K]^T (fp32 accuracy) ============
// CTA tile 128x128, 8 warps (4x2), warp tile 32x64, BK=32, cp.async double buffer.
#define ROWB 80                         // bytes per smem row (32 bf16 + 8 pad)
#define HALF_TILE (128 * ROWB)          // 10240 B
#define STAGE_BYTES (4 * HALF_TILE)     // Ahi|Alo|Bhi|Blo = 40960 B
#define GEMM_SMEM (2 * STAGE_BYTES)     // 81920 B (epilogue stage 128x132 f32 = 67.6KB fits)

template <int K>
__global__ __launch_bounds__(256, 2)
void k_gemm_mma(const __nv_bfloat16* __restrict__ Ahi, const __nv_bfloat16* __restrict__ Alo,
                const __nv_bfloat16* __restrict__ Bhi, const __nv_bfloat16* __restrict__ Blo,
                float* __restrict__ C) {
    extern __shared__ __align__(128) char smem[];
    const int tid = threadIdx.x;
    const int lane = tid & 31, wid = tid >> 5;
    const int warpm = wid & 3, warpn = wid >> 2;
    const int m0 = blockIdx.x * 128, n0 = blockIdx.y * 128;
    const uint32_t sb = cvta_smem(smem);
    const int NSTAGE = K / 32;

    float acc[2][8][4];
    #pragma unroll
    for (int i = 0; i < 2; i++)
        #pragma unroll
        for (int j = 0; j < 8; j++)
            #pragma unroll
            for (int q = 0; q < 4; q++) acc[i][j][q] = 0.f;

    auto prefetch = [&](int s) {
        uint32_t base = sb + (uint32_t)(s & 1) * STAGE_BYTES;
        #pragma unroll
        for (int l = 0; l < 2; l++) {
            int u = tid + l * 256;
            int row = u >> 2, ku = u & 3;
            uint32_t doff = (uint32_t)(row * ROWB + ku * 16);
            size_t goA = (size_t)(m0 + row) * K + s * 32 + ku * 8;
            size_t goB = (size_t)(n0 + row) * K + s * 32 + ku * 8;
            cp16(base + doff,                 Ahi + goA);
            cp16(base + HALF_TILE + doff,     Alo + goA);
            cp16(base + 2 * HALF_TILE + doff, Bhi + goB);
            cp16(base + 3 * HALF_TILE + doff, Blo + goB);
        }
        asm volatile("cp.async.commit_group;" ::: "memory");
    };

    prefetch(0);
    #pragma unroll 1
    for (int s = 0; s < NSTAGE; s++) {
        if (s + 1 < NSTAGE) {
            prefetch(s + 1);
            asm volatile("cp.async.wait_group 1;" ::: "memory");
        } else {
            asm volatile("cp.async.wait_group 0;" ::: "memory");
        }
        __syncthreads();

        const char* base = smem + (s & 1) * STAGE_BYTES;
        const char* pAhi = base;
        const char* pAlo = base + HALF_TILE;
        const char* pBhi = base + 2 * HALF_TILE;
        const char* pBlo = base + 3 * HALF_TILE;

        #pragma unroll
        for (int ks = 0; ks < 2; ks++) {
            const int kb = ks * 32 + (lane & 3) * 4;   // byte offset of this lane's k pair
            uint32_t ahi[2][4], alo[2][4];
            #pragma unroll
            for (int i = 0; i < 2; i++) {
                int r = warpm * 32 + i * 16 + (lane >> 2);
                int off = r * ROWB + kb;
                ahi[i][0] = *(const uint32_t*)(pAhi + off);
                ahi[i][1] = *(const uint32_t*)(pAhi + off + 8 * ROWB);
                ahi[i][2] = *(const uint32_t*)(pAhi + off + 16);
                ahi[i][3] = *(const uint32_t*)(pAhi + off + 8 * ROWB + 16);
                alo[i][0] = *(const uint32_t*)(pAlo + off);
                alo[i][1] = *(const uint32_t*)(pAlo + off + 8 * ROWB);
                alo[i][2] = *(const uint32_t*)(pAlo + off + 16);
                alo[i][3] = *(const uint32_t*)(pAlo + off + 8 * ROWB + 16);
            }
            #pragma unroll
            for (int j = 0; j < 8; j++) {
                int n = warpn * 64 + j * 8 + (lane >> 2);
                int off = n * ROWB + kb;
                uint32_t bh0 = *(const uint32_t*)(pBhi + off);
                uint32_t bh1 = *(const uint32_t*)(pBhi + off + 16);
                uint32_t bl0 = *(const uint32_t*)(pBlo + off);
                uint32_t bl1 = *(const uint32_t*)(pBlo + off + 16);
                #pragma unroll
                for (int i = 0; i < 2; i++) {
                    mma_bf16(acc[i][j], ahi[i], bh0, bh1);
                    mma_bf16(acc[i][j], ahi[i], bl0, bl1);
                    mma_bf16(acc[i][j], alo[i], bh0, bh1);
                }
            }
        }
        __syncthreads();
    }

    // epilogue: regs -> smem stage -> coalesced fp32 store
    float* stg = (float*)smem;   // [128][132]
    #pragma unroll
    for (int i = 0; i < 2; i++) {
        int r = warpm * 32 + i * 16 + (lane >> 2);
        #pragma unroll
        for (int j = 0; j < 8; j++) {
            int c = warpn * 64 + j * 8 + (lane & 3) * 2;
            stg[r * 132 + c]           = acc[i][j][0];
            stg[r * 132 + c + 1]       = acc[i][j][1];
            stg[(r + 8) * 132 + c]     = acc[i][j][2];
            stg[(r + 8) * 132 + c + 1] = acc[i][j][3];
        }
    }
    __syncthreads();
    #pragma unroll
    for (int l = 0; l < 16; l++) {
        int f = tid + l * 256;
        int row = f >> 5, c4 = f & 31;
        *(float4*)&C[(size_t)(m0 + row) * D + n0 + c4 * 4] = *(float4*)&stg[row * 132 + c4 * 4];
    }
}

// ---------------- layer-1 attention: per-graph GAT softmax+agg+bias+ELU -> bf16 hi/lo ----------------
__global__ __launch_bounds__(256)
void k_attn1(const float* __restrict__ asrc, const float* __restrict__ adst,
             const float* __restrict__ bias) {
    __shared__ float hsh[NPG][D];
    __shared__ float ssrc[NPG][NH], sdst[NPG][NH];
    __shared__ float ash[NH * HIDC], adsh[NH * HIDC];
    __shared__ float bsh[D];
    __shared__ unsigned short esh[MAXE];
    __shared__ unsigned short srcs[MAXE];
    __shared__ float alpha[MAXE * NH];
    __shared__ int deg[NPG], dstart[NPG + 1], dcur[NPG];
    __shared__ int s_nE;

    const int g = blockIdx.x;
    const int tid = threadIdx.x;
    const int base = g * NPG;

    const float* hp = g_h1lin + (size_t)base * D;
    for (int i = tid; i < NPG * D / 4; i += 256)
        ((float4*)&hsh[0][0])[i] = ((const float4*)hp)[i];
    for (int i = tid; i < NH * HIDC; i += 256) { ash[i] = asrc[i]; adsh[i] = adst[i]; }
    for (int i = tid; i < D; i += 256) bsh[i] = bias[i];
    if (tid < NPG) deg[tid] = 0;

    int off = g * CAP;
    int cnt = g_cur[g];
    if (cnt > CAP) cnt = CAP;
    for (int j = tid; j < cnt; j += 256) esh[j] = g_epack[off + j];
    if (tid < NPG) esh[cnt + tid] = (unsigned short)((tid << 5) | tid);  // self loops
    if (tid == 0) s_nE = cnt + NPG;
    __syncthreads();
    const int nE = s_nE;

    if (tid < 2 * NPG * NH) {
        int t = tid;
        int which = t >= NPG * NH;
        t -= which * NPG * NH;
        int i = t / NH, h = t % NH;
        const float* av = which ? &adsh[h * HIDC] : &ash[h * HIDC];
        float s = 0.f;
        #pragma unroll 8
        for (int c = 0; c < HIDC; c++) s += hsh[i][h * HIDC + c] * av[c];
        if (which) sdst[i][h] = s; else ssrc[i][h] = s;
    }
    for (int j = tid; j < nE; j += 256) atomicAdd(&deg[esh[j] & 31], 1);
    __syncthreads();
    if (tid == 0) {
        int a = 0;
        for (int i = 0; i < NPG; i++) { dstart[i] = a; dcur[i] = a; a += deg[i]; }
        dstart[NPG] = a;
    }
    __syncthreads();
    for (int j = tid; j < nE; j += 256) {
        unsigned short ev = esh[j];
        int dl = ev & 31;
        int p = atomicAdd(&dcur[dl], 1);
        srcs[p] = ev >> 5;
    }
    __syncthreads();
    if (tid < NPG * NH) {
        int dI = tid / NH, h = tid % NH;
        int p0 = dstart[dI], p1 = dstart[dI + 1];
        float sd = sdst[dI][h];
        float mx = -1e30f;
        for (int p = p0; p < p1; p++) {
            float v = ssrc[srcs[p]][h] + sd;
            v = (v >= 0.f) ? v : 0.2f * v;
            alpha[p * NH + h] = v;
            mx = fmaxf(mx, v);
        }
        float sum = 0.f;
        for (int p = p0; p < p1; p++) {
            float ex = expf(alpha[p * NH + h] - mx);
            alpha[p * NH + h] = ex;
            sum += ex;
        }
        float r = 1.f / (sum + 1e-16f);
        for (int p = p0; p < p1; p++) alpha[p * NH + h] *= r;
    }
    __syncthreads();
    const int c = tid;
    const int h = c >> 6;
    __nv_bfloat16* ohp = g_h1hi + (size_t)base * D;
    __nv_bfloat16* olp = g_h1lo + (size_t)base * D;
    for (int dI = 0; dI < NPG; dI++) {
        int p0 = dstart[dI], p1 = dstart[dI + 1];
        float acc = 0.f;
        for (int p = p0; p < p1; p++)
            acc += alpha[p * NH + h] * hsh[srcs[p]][c];
        float v = acc + bsh[c];
        v = (v > 0.f) ? v : expm1f(v);
        __nv_bfloat16 hv = __float2bfloat16(v);
        ohp[dI * D + c] = hv;
        olp[dI * D + c] = __float2bfloat16(v - __bfloat162float(hv));
    }
}

// ---------------- layer-2 attention at super node (dst=19) + MLP head ----------------
__global__ __launch_bounds__(256)
void k_attn2(const float* __restrict__ asrc, const float* __restrict__ adst,
             const float* __restrict__ bias2,
             const float* __restrict__ Wh, const float* __restrict__ bh,
             const float* __restrict__ Wc, const float* __restrict__ bc,
             float* __restrict__ out) {
    __shared__ float hsh[NPG][D];
    __shared__ float ssrc[NPG][NH];
    __shared__ float sd19[NH];
    __shared__ float ash[NH * HIDC], adsh[NH * HIDC];
    __shared__ float b2sh[D];
    __shared__ unsigned short l19[192];
    __shared__ int s_n19;
    __shared__ float al19[192 * NH];
    __shared__ float xs[D];
    __shared__ float hcls[HIDC];

    const int g = blockIdx.x;
    const int tid = threadIdx.x;
    const int base = g * NPG;

    const float* hp = g_h2lin + (size_t)base * D;
    for (int i = tid; i < NPG * D / 4; i += 256)
        ((float4*)&hsh[0][0])[i] = ((const float4*)hp)[i];
    for (int i = tid; i < NH * HIDC; i += 256) { ash[i] = asrc[i]; adsh[i] = adst[i]; }
    for (int i = tid; i < D; i += 256) b2sh[i] = bias2[i];
    if (tid == 0) s_n19 = 0;
    __syncthreads();

    int off = g * CAP;
    int cnt = g_cur[g];
    if (cnt > CAP) cnt = CAP;
    for (int j = tid; j < cnt; j += 256) {
        unsigned short ev = g_epack[off + j];
        if ((ev & 31) == 19) {
            int p = atomicAdd(&s_n19, 1);
            if (p < 191) l19[p] = ev >> 5;
        }
    }
    if (tid < NPG * NH) {
        int i = tid / NH, h = tid % NH;
        float s = 0.f;
        #pragma unroll 8
        for (int c = 0; c < HIDC; c++) s += hsh[i][h * HIDC + c] * ash[h * HIDC + c];
        ssrc[i][h] = s;
    } else if (tid < NPG * NH + NH) {
        int h = tid - NPG * NH;
        float s = 0.f;
        #pragma unroll 8
        for (int c = 0; c < HIDC; c++) s += hsh[19][h * HIDC + c] * adsh[h * HIDC + c];
        sd19[h] = s;
    }
    __syncthreads();
    if (tid == 0) {
        int m = s_n19 < 191 ? s_n19 : 191;
        l19[m] = 19;
        s_n19 = m + 1;
    }
    __syncthreads();
    const int ne = s_n19;

    if (tid < NH) {
        int h = tid;
        float sd = sd19[h];
        float mx = -1e30f;
        for (int p = 0; p < ne; p++) {
            float v = ssrc[l19[p]][h] + sd;
            v = (v >= 0.f) ? v : 0.2f * v;
            al19[p * NH + h] = v;
            mx = fmaxf(mx, v);
        }
        float sum = 0.f;
        for (int p = 0; p < ne; p++) {
            float ex = expf(al19[p * NH + h] - mx);
            al19[p * NH + h] = ex;
            sum += ex;
        }
        float r = 1.f / (sum + 1e-16f);
        for (int p = 0; p < ne; p++) al19[p * NH + h] *= r;
    }
    __syncthreads();
    {
        int c = tid, h = c >> 6;
        float acc = 0.f;
        for (int p = 0; p < ne; p++)
            acc += al19[p * NH + h] * hsh[l19[p]][c];
        float v = acc + b2sh[c];
        xs[c] = (v > 0.f) ? v : expm1f(v);
    }
    __syncthreads();
    const int w = tid >> 5, lane = tid & 31;
    #pragma unroll
    for (int jj = 0; jj < 8; jj++) {
        int j = w * 8 + jj;
        float a = 0.f;
        for (int k = lane; k < D; k += 32) a += xs[k] * Wh[j * D + k];
        #pragma unroll
        for (int o = 16; o; o >>= 1) a += __shfl_xor_sync(0xffffffffu, a, o);
        if (lane == 0) {
            float v = a + bh[j];
            hcls[j] = (v > 0.f) ? v : 0.f;
        }
    }
    __syncthreads();
    if (tid < 32) {
        float a = hcls[tid] * Wc[tid] + hcls[tid + 32] * Wc[tid + 32];
        #pragma unroll
        for (int o = 16; o; o >>= 1) a += __shfl_xor_sync(0xffffffffu, a, o);
        if (tid == 0) out[g] = a + bc[0];
    }
}

// ---------------- launcher ----------------
extern "C" void kernel_launch(void* const* d_in, const int* in_sizes, int n_in,
                              void* d_out, int out_size) {
    const float* x   = (const float*)d_in[0];
    const int*   ei  = (const int*)d_in[1];
    const float* W1  = (const float*)d_in[3];
    const float* a1s = (const float*)d_in[4];
    const float* a1d = (const float*)d_in[5];
    const float* b1  = (const float*)d_in[6];
    const float* W2  = (const float*)d_in[7];
    const float* a2s = (const float*)d_in[8];
    const float* a2d = (const float*)d_in[9];
    const float* b2  = (const float*)d_in[10];
    const float* Wh  = (const float*)d_in[11];
    const float* bh  = (const float*)d_in[12];
    const float* Wc  = (const float*)d_in[13];
    const float* bc  = (const float*)d_in[14];
    float* out = (float*)d_out;

    void *p_h1lin, *p_h2lin, *p_xhi, *p_xlo, *p_h1hi, *p_h1lo;
    void *p_w1hi, *p_w1lo, *p_w2hi, *p_w2lo;
    cudaGetSymbolAddress(&p_h1lin, g_h1lin);
    cudaGetSymbolAddress(&p_h2lin, g_h2lin);
    cudaGetSymbolAddress(&p_xhi, g_xhi);
    cudaGetSymbolAddress(&p_xlo, g_xlo);
    cudaGetSymbolAddress(&p_h1hi, g_h1hi);
    cudaGetSymbolAddress(&p_h1lo, g_h1lo);
    cudaGetSymbolAddress(&p_w1hi, g_w1hi);
    cudaGetSymbolAddress(&p_w1lo, g_w1lo);
    cudaGetSymbolAddress(&p_w2hi, g_w2hi);
    cudaGetSymbolAddress(&p_w2lo, g_w2lo);

    cudaFuncSetAttribute(k_gemm_mma<IND>, cudaFuncAttributeMaxDynamicSharedMemorySize, GEMM_SMEM);
    cudaFuncSetAttribute(k_gemm_mma<D>,   cudaFuncAttributeMaxDynamicSharedMemorySize, GEMM_SMEM);

    k_zero<<<(NG + 255) / 256, 256>>>();
    k_scatter<<<(NEDGES + 255) / 256, 256>>>(ei);

    k_split<<<(NNODES * IND / 4 + 255) / 256, 256>>>(x, (__nv_bfloat16*)p_xhi,
                                                     (__nv_bfloat16*)p_xlo, NNODES * IND / 4);
    k_split<<<(D * IND / 4 + 255) / 256, 256>>>(W1, (__nv_bfloat16*)p_w1hi,
                                                (__nv_bfloat16*)p_w1lo, D * IND / 4);
    k_split<<<(D * D / 4 + 255) / 256, 256>>>(W2, (__nv_bfloat16*)p_w2hi,
                                              (__nv_bfloat16*)p_w2lo, D * D / 4);

    k_gemm_mma<IND><<<dim3(NNODES / 128, 2), 256, GEMM_SMEM>>>(
        (const __nv_bfloat16*)p_xhi, (const __nv_bfloat16*)p_xlo,
        (const __nv_bfloat16*)p_w1hi, (const __nv_bfloat16*)p_w1lo, (float*)p_h1lin);
    k_attn1<<<NG, 256>>>(a1s, a1d, b1);
    k_gemm_mma<D><<<dim3(NNODES / 128, 2), 256, GEMM_SMEM>>>(
        (const __nv_bfloat16*)p_h1hi, (const __nv_bfloat16*)p_h1lo,
        (const __nv_bfloat16*)p_w2hi, (const __nv_bfloat16*)p_w2lo, (float*)p_h2lin);
    k_attn2<<<NG, 256>>>(a2s, a2d, b2, Wh, bh, Wc, bc, out);
}

// round 4
// speedup vs baseline: 1.5104x; 1.0875x over previous
#include <cuda_runtime.h>
#include <cuda_fp16.h>
#include <math.h>
#include <stdint.h>

#define NNODES 81920
#define NEDGES 1310720
#define NG     4096
#define NPG    20
#define IND    128
#define D      256
#define HIDC   64
#define NH     4
#define CAP    512            // per-graph edge capacity (mean 320, +10.7 sigma)
#define MAXE   (CAP + NPG)    // incl. self loops

// ---------------- scratch (no allocations allowed) ----------------
__device__ __align__(16) float g_h1lin[NNODES * D];
__device__ __align__(16) float g_h2lin[NNODES * D];
__device__ __align__(16) __half g_xhi[NNODES * IND];
__device__ __align__(16) __half g_xlo[NNODES * IND];
__device__ __align__(16) __half g_h1hi[NNODES * D];
__device__ __align__(16) __half g_h1lo[NNODES * D];
__device__ __align__(16) __half g_w1h[D * IND];
__device__ __align__(16) __half g_w2h[D * D];
__device__ int g_cur[NG];
__device__ unsigned short g_epack[NG * CAP];

// ================= helpers =================
__device__ __forceinline__ uint32_t cvta_smem(const void* p) {
    uint32_t a;
    asm("{ .reg .u64 t; cvta.to.shared.u64 t, %1; cvt.u32.u64 %0, t; }" : "=r"(a) : "l"(p));
    return a;
}
__device__ __forceinline__ void cp16(uint32_t dst, const void* src) {
    asm volatile("cp.async.cg.shared.global [%0], [%1], 16;" :: "r"(dst), "l"(src) : "memory");
}
__device__ __forceinline__ void mma_f16(float* d, const uint32_t* a, uint32_t b0, uint32_t b1) {
    asm volatile(
        "mma.sync.aligned.m16n8k16.row.col.f32.f16.f16.f32 "
        "{%0,%1,%2,%3}, {%4,%5,%6,%7}, {%8,%9}, {%0,%1,%2,%3};"
        : "+f"(d[0]), "+f"(d[1]), "+f"(d[2]), "+f"(d[3])
        : "r"(a[0]), "r"(a[1]), "r"(a[2]), "r"(a[3]), "r"(b0), "r"(b1));
}

// ---------------- edge preprocessing ----------------
__global__ void k_zero() {
    int i = blockIdx.x * blockDim.x + threadIdx.x;
    if (i < NG) g_cur[i] = 0;
}

__global__ void k_scatter(const int* __restrict__ ei) {
    int e = blockIdx.x * blockDim.x + threadIdx.x;
    if (e < NEDGES) {
        int s = ei[e];
        int d = ei[NEDGES + e];
        int g = d / NPG;
        int p = atomicAdd(&g_cur[g], 1);
        if (p < CAP)
            g_epack[g * CAP + p] = (unsigned short)(((s - g * NPG) << 5) | (d - g * NPG));
    }
}

// ---------------- fp32 -> fp16 hi/lo split, and single convert ----------------
__global__ void k_split(const float* __restrict__ src, __half* __restrict__ hi,
                        __half* __restrict__ lo, int n4) {
    int i = blockIdx.x * blockDim.x + threadIdx.x;
    if (i < n4) {
        float4 v = ((const float4*)src)[i];
        __half h[4], l[4];
        float vv[4] = {v.x, v.y, v.z, v.w};
        #pragma unroll
        for (int j = 0; j < 4; j++) {
            h[j] = __float2half(vv[j]);
            l[j] = __float2half(vv[j] - __half2float(h[j]));
        }
        ((uint2*)hi)[i] = *(uint2*)h;
        ((uint2*)lo)[i] = *(uint2*)l;
    }
}

__global__ void k_cvt(const float* __restrict__ src, __half* __restrict__ dst, int n4) {
    int i = blockIdx.x * blockDim.x + threadIdx.x;
    if (i < n4) {
        float4 v = ((const float4*)src)[i];
        __half h[4] = {__float2half(v.x), __float2half(v.y),
                       __float2half(v.z), __float2half(v.w)};
        ((uint2*)dst)[i] = *(uint2*)h;
    }
}

// ============ fp16x2 mma.sync GEMM: C[M,256] = (Ahi+Alo)[M,K] * Bh[256,K]^T ============
// CTA tile 128x128, 8 warps (4x2), warp tile 32x64, BK=32, cp.async double buffer, 2 MMAs/step.
#define ROWB 80                         // bytes per smem row (32 fp16 + 16B pad)
#define HALF_TILE (128 * ROWB)          // 10240 B
#define STAGE_BYTES (3 * HALF_TILE)     // Ahi|Alo|B = 30720 B
#define GEMM_SMEM 69632                 // max(2*STAGE=61440, epilogue 128*132*4=67584)

template <int K>
__global__ __launch_bounds__(256, 2)
void k_gemm_mma(const __half* __restrict__ Ahi, const __half* __restrict__ Alo,
                const __half* __restrict__ Bh, float* __restrict__ C) {
    extern __shared__ __align__(128) char smem[];
    const int tid = threadIdx.x;
    const int lane = tid & 31, wid = tid >> 5;
    const int warpm = wid & 3, warpn = wid >> 2;
    const int m0 = blockIdx.x * 128, n0 = blockIdx.y * 128;
    const uint32_t sb = cvta_smem(smem);
    const int NSTAGE = K / 32;

    float acc[2][8][4];
    #pragma unroll
    for (int i = 0; i < 2; i++)
        #pragma unroll
        for (int j = 0; j < 8; j++)
            #pragma unroll
            for (int q = 0; q < 4; q++) acc[i][j][q] = 0.f;

    auto prefetch = [&](int s) {
        uint32_t base = sb + (uint32_t)(s & 1) * STAGE_BYTES;
        #pragma unroll
        for (int l = 0; l < 2; l++) {
            int u = tid + l * 256;
            int row = u >> 2, ku = u & 3;
            uint32_t doff = (uint32_t)(row * ROWB + ku * 16);
            size_t goA = (size_t)(m0 + row) * K + s * 32 + ku * 8;
            size_t goB = (size_t)(n0 + row) * K + s * 32 + ku * 8;
            cp16(base + doff,                 Ahi + goA);
            cp16(base + HALF_TILE + doff,     Alo + goA);
            cp16(base + 2 * HALF_TILE + doff, Bh + goB);
        }
        asm volatile("cp.async.commit_group;" ::: "memory");
    };

    prefetch(0);
    #pragma unroll 1
    for (int s = 0; s < NSTAGE; s++) {
        if (s + 1 < NSTAGE) {
            prefetch(s + 1);
            asm volatile("cp.async.wait_group 1;" ::: "memory");
        } else {
            asm volatile("cp.async.wait_group 0;" ::: "memory");
        }
        __syncthreads();

        const char* base = smem + (s & 1) * STAGE_BYTES;
        const char* pAhi = base;
        const char* pAlo = base + HALF_TILE;
        const char* pB   = base + 2 * HALF_TILE;

        #pragma unroll
        for (int ks = 0; ks < 2; ks++) {
            const int kb = ks * 32 + (lane & 3) * 4;   // byte offset of this lane's k pair
            uint32_t ahi[2][4], alo[2][4];
            #pragma unroll
            for (int i = 0; i < 2; i++) {
                int r = warpm * 32 + i * 16 + (lane >> 2);
                int off = r * ROWB + kb;
                ahi[i][0] = *(const uint32_t*)(pAhi + off);
                ahi[i][1] = *(const uint32_t*)(pAhi + off + 8 * ROWB);
                ahi[i][2] = *(const uint32_t*)(pAhi + off + 16);
                ahi[i][3] = *(const uint32_t*)(pAhi + off + 8 * ROWB + 16);
                alo[i][0] = *(const uint32_t*)(pAlo + off);
                alo[i][1] = *(const uint32_t*)(pAlo + off + 8 * ROWB);
                alo[i][2] = *(const uint32_t*)(pAlo + off + 16);
                alo[i][3] = *(const uint32_t*)(pAlo + off + 8 * ROWB + 16);
            }
            #pragma unroll
            for (int j = 0; j < 8; j++) {
                int n = warpn * 64 + j * 8 + (lane >> 2);
                int off = n * ROWB + kb;
                uint32_t b0 = *(const uint32_t*)(pB + off);
                uint32_t b1 = *(const uint32_t*)(pB + off + 16);
                #pragma unroll
                for (int i = 0; i < 2; i++) {
                    mma_f16(acc[i][j], ahi[i], b0, b1);
                    mma_f16(acc[i][j], alo[i], b0, b1);
                }
            }
        }
        __syncthreads();
    }

    // epilogue: regs -> smem stage -> coalesced fp32 store
    float* stg = (float*)smem;   // [128][132]
    #pragma unroll
    for (int i = 0; i < 2; i++) {
        int r = warpm * 32 + i * 16 + (lane >> 2);
        #pragma unroll
        for (int j = 0; j < 8; j++) {
            int c = warpn * 64 + j * 8 + (lane & 3) * 2;
            stg[r * 132 + c]           = acc[i][j][0];
            stg[r * 132 + c + 1]       = acc[i][j][1];
            stg[(r + 8) * 132 + c]     = acc[i][j][2];
            stg[(r + 8) * 132 + c + 1] = acc[i][j][3];
        }
    }
    __syncthreads();
    #pragma unroll
    for (int l = 0; l < 16; l++) {
        int f = tid + l * 256;
        int row = f >> 5, c4 = f & 31;
        *(float4*)&C[(size_t)(m0 + row) * D + n0 + c4 * 4] = *(float4*)&stg[row * 132 + c4 * 4];
    }
}

// ---------------- layer-1 attention: per-graph GAT softmax+agg+bias+ELU -> fp16 hi/lo ----------------
__global__ __launch_bounds__(256)
void k_attn1(const float* __restrict__ asrc, const float* __restrict__ adst,
             const float* __restrict__ bias) {
    __shared__ float hsh[NPG][D];
    __shared__ float ssrc[NPG][NH], sdst[NPG][NH];
    __shared__ float ash[NH * HIDC], adsh[NH * HIDC];
    __shared__ float bsh[D];
    __shared__ unsigned short esh[MAXE];
    __shared__ unsigned short srcs[MAXE];
    __shared__ float alpha[MAXE * NH];
    __shared__ int deg[NPG], dstart[NPG + 1], dcur[NPG];
    __shared__ int s_nE;

    const int g = blockIdx.x;
    const int tid = threadIdx.x;
    const int base = g * NPG;

    const float* hp = g_h1lin + (size_t)base * D;
    for (int i = tid; i < NPG * D / 4; i += 256)
        ((float4*)&hsh[0][0])[i] = ((const float4*)hp)[i];
    for (int i = tid; i < NH * HIDC; i += 256) { ash[i] = asrc[i]; adsh[i] = adst[i]; }
    for (int i = tid; i < D; i += 256) bsh[i] = bias[i];
    if (tid < NPG) deg[tid] = 0;

    int off = g * CAP;
    int cnt = g_cur[g];
    if (cnt > CAP) cnt = CAP;
    for (int j = tid; j < cnt; j += 256) esh[j] = g_epack[off + j];
    if (tid < NPG) esh[cnt + tid] = (unsigned short)((tid << 5) | tid);  // self loops
    if (tid == 0) s_nE = cnt + NPG;
    __syncthreads();
    const int nE = s_nE;

    if (tid < 2 * NPG * NH) {
        int t = tid;
        int which = t >= NPG * NH;
        t -= which * NPG * NH;
        int i = t / NH, h = t % NH;
        const float* av = which ? &adsh[h * HIDC] : &ash[h * HIDC];
        float s = 0.f;
        #pragma unroll 8
        for (int c = 0; c < HIDC; c++) s += hsh[i][h * HIDC + c] * av[c];
        if (which) sdst[i][h] = s; else ssrc[i][h] = s;
    }
    for (int j = tid; j < nE; j += 256) atomicAdd(&deg[esh[j] & 31], 1);
    __syncthreads();
    if (tid == 0) {
        int a = 0;
        for (int i = 0; i < NPG; i++) { dstart[i] = a; dcur[i] = a; a += deg[i]; }
        dstart[NPG] = a;
    }
    __syncthreads();
    for (int j = tid; j < nE; j += 256) {
        unsigned short ev = esh[j];
        int dl = ev & 31;
        int p = atomicAdd(&dcur[dl], 1);
        srcs[p] = ev >> 5;
    }
    __syncthreads();
    if (tid < NPG * NH) {
        int dI = tid / NH, h = tid % NH;
        int p0 = dstart[dI], p1 = dstart[dI + 1];
        float sd = sdst[dI][h];
        float mx = -1e30f;
        for (int p = p0; p < p1; p++) {
            float v = ssrc[srcs[p]][h] + sd;
            v = (v >= 0.f) ? v : 0.2f * v;
            alpha[p * NH + h] = v;
            mx = fmaxf(mx, v);
        }
        float sum = 0.f;
        for (int p = p0; p < p1; p++) {
            float ex = expf(alpha[p * NH + h] - mx);
            alpha[p * NH + h] = ex;
            sum += ex;
        }
        float r = 1.f / (sum + 1e-16f);
        for (int p = p0; p < p1; p++) alpha[p * NH + h] *= r;
    }
    __syncthreads();
    const int c = tid;
    const int h = c >> 6;
    __half* ohp = g_h1hi + (size_t)base * D;
    __half* olp = g_h1lo + (size_t)base * D;
    for (int dI = 0; dI < NPG; dI++) {
        int p0 = dstart[dI], p1 = dstart[dI + 1];
        float acc = 0.f;
        for (int p = p0; p < p1; p++)
            acc += alpha[p * NH + h] * hsh[srcs[p]][c];
        float v = acc + bsh[c];
        v = (v > 0.f) ? v : expm1f(v);
        __half hv = __float2half(v);
        ohp[dI * D + c] = hv;
        olp[dI * D + c] = __float2half(v - __half2float(hv));
    }
}

// ---------------- layer-2 attention at super node (dst=19) + MLP head ----------------
__global__ __launch_bounds__(256)
void k_attn2(const float* __restrict__ asrc, const float* __restrict__ adst,
             const float* __restrict__ bias2,
             const float* __restrict__ Wh, const float* __restrict__ bh,
             const float* __restrict__ Wc, const float* __restrict__ bc,
             float* __restrict__ out) {
    __shared__ float hsh[NPG][D];
    __shared__ float ssrc[NPG][NH];
    __shared__ float sd19[NH];
    __shared__ float ash[NH * HIDC], adsh[NH * HIDC];
    __shared__ float b2sh[D];
    __shared__ unsigned short l19[192];
    __shared__ int s_n19;
    __shared__ float al19[192 * NH];
    __shared__ float xs[D];
    __shared__ float hcls[HIDC];

    const int g = blockIdx.x;
    const int tid = threadIdx.x;
    const int base = g * NPG;

    const float* hp = g_h2lin + (size_t)base * D;
    for (int i = tid; i < NPG * D / 4; i += 256)
        ((float4*)&hsh[0][0])[i] = ((const float4*)hp)[i];
    for (int i = tid; i < NH * HIDC; i += 256) { ash[i] = asrc[i]; adsh[i] = adst[i]; }
    for (int i = tid; i < D; i += 256) b2sh[i] = bias2[i];
    if (tid == 0) s_n19 = 0;
    __syncthreads();

    int off = g * CAP;
    int cnt = g_cur[g];
    if (cnt > CAP) cnt = CAP;
    for (int j = tid; j < cnt; j += 256) {
        unsigned short ev = g_epack[off + j];
        if ((ev & 31) == 19) {
            int p = atomicAdd(&s_n19, 1);
            if (p < 191) l19[p] = ev >> 5;
        }
    }
    if (tid < NPG * NH) {
        int i = tid / NH, h = tid % NH;
        float s = 0.f;
        #pragma unroll 8
        for (int c = 0; c < HIDC; c++) s += hsh[i][h * HIDC + c] * ash[h * HIDC + c];
        ssrc[i][h] = s;
    } else if (tid < NPG * NH + NH) {
        int h = tid - NPG * NH;
        float s = 0.f;
        #pragma unroll 8
        for (int c = 0; c < HIDC; c++) s += hsh[19][h * HIDC + c] * adsh[h * HIDC + c];
        sd19[h] = s;
    }
    __syncthreads();
    if (tid == 0) {
        int m = s_n19 < 191 ? s_n19 : 191;
        l19[m] = 19;
        s_n19 = m + 1;
    }
    __syncthreads();
    const int ne = s_n19;

    if (tid < NH) {
        int h = tid;
        float sd = sd19[h];
        float mx = -1e30f;
        for (int p = 0; p < ne; p++) {
            float v = ssrc[l19[p]][h] + sd;
            v = (v >= 0.f) ? v : 0.2f * v;
            al19[p * NH + h] = v;
            mx = fmaxf(mx, v);
        }
        float sum = 0.f;
        for (int p = 0; p < ne; p++) {
            float ex = expf(al19[p * NH + h] - mx);
            al19[p * NH + h] = ex;
            sum += ex;
        }
        float r = 1.f / (sum + 1e-16f);
        for (int p = 0; p < ne; p++) al19[p * NH + h] *= r;
    }
    __syncthreads();
    {
        int c = tid, h = c >> 6;
        float acc = 0.f;
        for (int p = 0; p < ne; p++)
            acc += al19[p * NH + h] * hsh[l19[p]][c];
        float v = acc + b2sh[c];
        xs[c] = (v > 0.f) ? v : expm1f(v);
    }
    __syncthreads();
    const int w = tid >> 5, lane = tid & 31;
    #pragma unroll
    for (int jj = 0; jj < 8; jj++) {
        int j = w * 8 + jj;
        float a = 0.f;
        for (int k = lane; k < D; k += 32) a += xs[k] * Wh[j * D + k];
        #pragma unroll
        for (int o = 16; o; o >>= 1) a += __shfl_xor_sync(0xffffffffu, a, o);
        if (lane == 0) {
            float v = a + bh[j];
            hcls[j] = (v > 0.f) ? v : 0.f;
        }
    }
    __syncthreads();
    if (tid < 32) {
        float a = hcls[tid] * Wc[tid] + hcls[tid + 32] * Wc[tid + 32];
        #pragma unroll
        for (int o = 16; o; o >>= 1) a += __shfl_xor_sync(0xffffffffu, a, o);
        if (tid == 0) out[g] = a + bc[0];
    }
}

// ---------------- launcher ----------------
extern "C" void kernel_launch(void* const* d_in, const int* in_sizes, int n_in,
                              void* d_out, int out_size) {
    const float* x   = (const float*)d_in[0];
    const int*   ei  = (const int*)d_in[1];
    const float* W1  = (const float*)d_in[3];
    const float* a1s = (const float*)d_in[4];
    const float* a1d = (const float*)d_in[5];
    const float* b1  = (const float*)d_in[6];
    const float* W2  = (const float*)d_in[7];
    const float* a2s = (const float*)d_in[8];
    const float* a2d = (const float*)d_in[9];
    const float* b2  = (const float*)d_in[10];
    const float* Wh  = (const float*)d_in[11];
    const float* bh  = (const float*)d_in[12];
    const float* Wc  = (const float*)d_in[13];
    const float* bc  = (const float*)d_in[14];
    float* out = (float*)d_out;

    void *p_h1lin, *p_h2lin, *p_xhi, *p_xlo, *p_h1hi, *p_h1lo, *p_w1h, *p_w2h;
    cudaGetSymbolAddress(&p_h1lin, g_h1lin);
    cudaGetSymbolAddress(&p_h2lin, g_h2lin);
    cudaGetSymbolAddress(&p_xhi, g_xhi);
    cudaGetSymbolAddress(&p_xlo, g_xlo);
    cudaGetSymbolAddress(&p_h1hi, g_h1hi);
    cudaGetSymbolAddress(&p_h1lo, g_h1lo);
    cudaGetSymbolAddress(&p_w1h, g_w1h);
    cudaGetSymbolAddress(&p_w2h, g_w2h);

    cudaFuncSetAttribute(k_gemm_mma<IND>, cudaFuncAttributeMaxDynamicSharedMemorySize, GEMM_SMEM);
    cudaFuncSetAttribute(k_gemm_mma<D>,   cudaFuncAttributeMaxDynamicSharedMemorySize, GEMM_SMEM);

    // launch order chosen so gemm1 sits at capture index 3 (ncu -s window)
    k_split<<<(NNODES * IND / 4 + 255) / 256, 256>>>(x, (__half*)p_xhi, (__half*)p_xlo,
                                                     NNODES * IND / 4);
    k_cvt<<<(D * IND / 4 + 255) / 256, 256>>>(W1, (__half*)p_w1h, D * IND / 4);
    k_cvt<<<(D * D / 4 + 255) / 256, 256>>>(W2, (__half*)p_w2h, D * D / 4);

    k_gemm_mma<IND><<<dim3(NNODES / 128, 2), 256, GEMM_SMEM>>>(
        (const __half*)p_xhi, (const __half*)p_xlo, (const __half*)p_w1h, (float*)p_h1lin);

    k_zero<<<(NG + 255) / 256, 256>>>();
    k_scatter<<<(NEDGES + 255) / 256, 256>>>(ei);

    k_attn1<<<NG, 256>>>(a1s, a1d, b1);
    k_gemm_mma<D><<<dim3(NNODES / 128, 2), 256, GEMM_SMEM>>>(
        (const __half*)p_h1hi, (const __half*)p_h1lo, (const __half*)p_w2h, (float*)p_h2lin);
    k_attn2<<<NG, 256>>>(a2s, a2d, b2, Wh, bh, Wc, bc, out);
}

// round 5
// speedup vs baseline: 1.7258x; 1.1426x over previous
#include <cuda_runtime.h>
#include <cuda_fp16.h>
#include <math.h>
#include <stdint.h>

#define NNODES 81920
#define NEDGES 1310720
#define NG     4096
#define NPG    20
#define IND    128
#define D      256
#define HIDC   64
#define NH     4
#define CAP    512            // per-graph edge capacity (mean 320, +10.7 sigma)
#define MAXE   (CAP + NPG)    // incl. self loops

// ---------------- scratch (no allocations allowed) ----------------
__device__ __align__(16) float g_h1lin[NNODES * D];   // gemm1 out; reused as xs after attn1
__device__ __align__(16) float g_h2lin[NNODES * D];
__device__ __align__(16) __half g_xhi[NNODES * IND];
__device__ __align__(16) __half g_xlo[NNODES * IND];
__device__ __align__(16) __half g_h1hi[NNODES * D];
__device__ __align__(16) __half g_h1lo[NNODES * D];
__device__ __align__(16) __half g_w1h[D * IND];
__device__ __align__(16) __half g_w2h[D * D];
__device__ __align__(16) float g_WhT[D * HIDC];
__device__ int g_cur[NG];
__device__ unsigned short g_epack[NG * CAP];

// ================= helpers =================
__device__ __forceinline__ uint32_t cvta_smem(const void* p) {
    uint32_t a;
    asm("{ .reg .u64 t; cvta.to.shared.u64 t, %1; cvt.u32.u64 %0, t; }" : "=r"(a) : "l"(p));
    return a;
}
__device__ __forceinline__ void cp16(uint32_t dst, const void* src) {
    asm volatile("cp.async.cg.shared.global [%0], [%1], 16;" :: "r"(dst), "l"(src) : "memory");
}
__device__ __forceinline__ void mma_f16(float* d, const uint32_t* a, uint32_t b0, uint32_t b1) {
    asm volatile(
        "mma.sync.aligned.m16n8k16.row.col.f32.f16.f16.f32 "
        "{%0,%1,%2,%3}, {%4,%5,%6,%7}, {%8,%9}, {%0,%1,%2,%3};"
        : "+f"(d[0]), "+f"(d[1]), "+f"(d[2]), "+f"(d[3])
        : "r"(a[0]), "r"(a[1]), "r"(a[2]), "r"(a[3]), "r"(b0), "r"(b1));
}
__device__ __forceinline__ void atomicMaxF(float* a, float v) {
    if (v >= 0.f) atomicMax((int*)a, __float_as_int(v));
    else atomicMin((unsigned int*)a, __float_as_uint(v));
}

// ---------------- edge scatter (g_cur must be 0 on entry; attn2a resets it) ----------------
__global__ void k_scatter(const int* __restrict__ ei) {
    int e = blockIdx.x * blockDim.x + threadIdx.x;
    if (e < NEDGES) {
        int s = ei[e];
        int d = ei[NEDGES + e];
        int g = d / NPG;
        int p = atomicAdd(&g_cur[g], 1);
        if (p < CAP)
            g_epack[g * CAP + p] = (unsigned short)(((s - g * NPG) << 5) | (d - g * NPG));
    }
}

// ---------------- fused: x -> fp16 hi/lo split  +  W1 -> fp16 ----------------
#define N4X (NNODES * IND / 4)
#define N4W1 (D * IND / 4)
__global__ void k_prep1(const float* __restrict__ x, const float* __restrict__ W1) {
    int i = blockIdx.x * blockDim.x + threadIdx.x;
    if (i < N4X) {
        float4 v = ((const float4*)x)[i];
        __half h[4], l[4];
        float vv[4] = {v.x, v.y, v.z, v.w};
        #pragma unroll
        for (int j = 0; j < 4; j++) {
            h[j] = __float2half(vv[j]);
            l[j] = __float2half(vv[j] - __half2float(h[j]));
        }
        ((uint2*)g_xhi)[i] = *(uint2*)h;
        ((uint2*)g_xlo)[i] = *(uint2*)l;
    } else if (i < N4X + N4W1) {
        int j = i - N4X;
        float4 v = ((const float4*)W1)[j];
        __half h[4] = {__float2half(v.x), __float2half(v.y),
                       __float2half(v.z), __float2half(v.w)};
        ((uint2*)g_w1h)[j] = *(uint2*)h;
    }
}

// ---------------- fused: W2 -> fp16  +  Wh transpose ----------------
#define N4W2 (D * D / 4)
__global__ void k_prep2(const float* __restrict__ W2, const float* __restrict__ Wh) {
    int i = blockIdx.x * blockDim.x + threadIdx.x;
    if (i < N4W2) {
        float4 v = ((const float4*)W2)[i];
        __half h[4] = {__float2half(v.x), __float2half(v.y),
                       __float2half(v.z), __float2half(v.w)};
        ((uint2*)g_w2h)[i] = *(uint2*)h;
    } else if (i < N4W2 + D * HIDC) {
        int j = i - N4W2;           // j = k*64 + jc  (output index)
        int k = j >> 6, jc = j & 63;
        g_WhT[j] = Wh[jc * D + k];
    }
}

// ============ fp16x2 mma.sync GEMM: C[M,256] = (Ahi+Alo)[M,K] * Bh[256,K]^T ============
#define ROWB 80
#define HALF_TILE (128 * ROWB)
#define STAGE_BYTES (3 * HALF_TILE)
#define GEMM_SMEM 69632

template <int K>
__global__ __launch_bounds__(256, 2)
void k_gemm_mma(const __half* __restrict__ Ahi, const __half* __restrict__ Alo,
                const __half* __restrict__ Bh, float* __restrict__ C) {
    extern __shared__ __align__(128) char smem[];
    const int tid = threadIdx.x;
    const int lane = tid & 31, wid = tid >> 5;
    const int warpm = wid & 3, warpn = wid >> 2;
    const int m0 = blockIdx.x * 128, n0 = blockIdx.y * 128;
    const uint32_t sb = cvta_smem(smem);
    const int NSTAGE = K / 32;

    float acc[2][8][4];
    #pragma unroll
    for (int i = 0; i < 2; i++)
        #pragma unroll
        for (int j = 0; j < 8; j++)
            #pragma unroll
            for (int q = 0; q < 4; q++) acc[i][j][q] = 0.f;

    auto prefetch = [&](int s) {
        uint32_t base = sb + (uint32_t)(s & 1) * STAGE_BYTES;
        #pragma unroll
        for (int l = 0; l < 2; l++) {
            int u = tid + l * 256;
            int row = u >> 2, ku = u & 3;
            uint32_t doff = (uint32_t)(row * ROWB + ku * 16);
            size_t goA = (size_t)(m0 + row) * K + s * 32 + ku * 8;
            size_t goB = (size_t)(n0 + row) * K + s * 32 + ku * 8;
            cp16(base + doff,                 Ahi + goA);
            cp16(base + HALF_TILE + doff,     Alo + goA);
            cp16(base + 2 * HALF_TILE + doff, Bh + goB);
        }
        asm volatile("cp.async.commit_group;" ::: "memory");
    };

    prefetch(0);
    #pragma unroll 1
    for (int s = 0; s < NSTAGE; s++) {
        if (s + 1 < NSTAGE) {
            prefetch(s + 1);
            asm volatile("cp.async.wait_group 1;" ::: "memory");
        } else {
            asm volatile("cp.async.wait_group 0;" ::: "memory");
        }
        __syncthreads();

        const char* base = smem + (s & 1) * STAGE_BYTES;
        const char* pAhi = base;
        const char* pAlo = base + HALF_TILE;
        const char* pB   = base + 2 * HALF_TILE;

        #pragma unroll
        for (int ks = 0; ks < 2; ks++) {
            const int kb = ks * 32 + (lane & 3) * 4;
            uint32_t ahi[2][4], alo[2][4];
            #pragma unroll
            for (int i = 0; i < 2; i++) {
                int r = warpm * 32 + i * 16 + (lane >> 2);
                int off = r * ROWB + kb;
                ahi[i][0] = *(const uint32_t*)(pAhi + off);
                ahi[i][1] = *(const uint32_t*)(pAhi + off + 8 * ROWB);
                ahi[i][2] = *(const uint32_t*)(pAhi + off + 16);
                ahi[i][3] = *(const uint32_t*)(pAhi + off + 8 * ROWB + 16);
                alo[i][0] = *(const uint32_t*)(pAlo + off);
                alo[i][1] = *(const uint32_t*)(pAlo + off + 8 * ROWB);
                alo[i][2] = *(const uint32_t*)(pAlo + off + 16);
                alo[i][3] = *(const uint32_t*)(pAlo + off + 8 * ROWB + 16);
            }
            #pragma unroll
            for (int j = 0; j < 8; j++) {
                int n = warpn * 64 + j * 8 + (lane >> 2);
                int off = n * ROWB + kb;
                uint32_t b0 = *(const uint32_t*)(pB + off);
                uint32_t b1 = *(const uint32_t*)(pB + off + 16);
                #pragma unroll
                for (int i = 0; i < 2; i++) {
                    mma_f16(acc[i][j], ahi[i], b0, b1);
                    mma_f16(acc[i][j], alo[i], b0, b1);
                }
            }
        }
        __syncthreads();
    }

    float* stg = (float*)smem;   // [128][132]
    #pragma unroll
    for (int i = 0; i < 2; i++) {
        int r = warpm * 32 + i * 16 + (lane >> 2);
        #pragma unroll
        for (int j = 0; j < 8; j++) {
            int c = warpn * 64 + j * 8 + (lane & 3) * 2;
            stg[r * 132 + c]           = acc[i][j][0];
            stg[r * 132 + c + 1]       = acc[i][j][1];
            stg[(r + 8) * 132 + c]     = acc[i][j][2];
            stg[(r + 8) * 132 + c + 1] = acc[i][j][3];
        }
    }
    __syncthreads();
    #pragma unroll
    for (int l = 0; l < 16; l++) {
        int f = tid + l * 256;
        int row = f >> 5, c4 = f & 31;
        *(float4*)&C[(size_t)(m0 + row) * D + n0 + c4 * 4] = *(float4*)&stg[row * 132 + c4 * 4];
    }
}

// ---------------- layer-1 attention (restructured) ----------------
// hT[k][src][h]: transposed features; aggregation does 3 LDS per 4 channels.
__global__ __launch_bounds__(256)
void k_attn1(const float* __restrict__ asrc, const float* __restrict__ adst,
             const float* __restrict__ bias) {
    __shared__ float hT[64 * 84];             // [k][21 src pad][4 h]
    __shared__ float alpha[MAXE][NH];
    __shared__ float ssrc[NPG][NH], sdst[NPG][NH];
    __shared__ float ash[NH * HIDC], adsh[NH * HIDC], bsh[D];
    __shared__ float mxs[NPG * NH], dnm[NPG * NH];
    __shared__ unsigned short esh[MAXE], srcs[MAXE], dst16[MAXE];
    __shared__ int deg[NPG], dstart[NPG + 1], dcur[NPG], s_nE;

    const int g = blockIdx.x;
    const int tid = threadIdx.x;
    const int base = g * NPG;

    // phase 0: loads + transpose + init
    const float* hp = g_h1lin + (size_t)base * D;
    for (int i = tid; i < NPG * D / 4; i += 256) {
        float4 v = ((const float4*)hp)[i];
        int c0 = (i << 2) & 255, src = (i << 2) >> 8;
        int h = c0 >> 6, k0 = c0 & 63;
        hT[((k0 + 0) * 21 + src) * 4 + h] = v.x;
        hT[((k0 + 1) * 21 + src) * 4 + h] = v.y;
        hT[((k0 + 2) * 21 + src) * 4 + h] = v.z;
        hT[((k0 + 3) * 21 + src) * 4 + h] = v.w;
    }
    for (int i = tid; i < NH * HIDC; i += 256) { ash[i] = asrc[i]; adsh[i] = adst[i]; }
    for (int i = tid; i < D; i += 256) bsh[i] = bias[i];
    if (tid < NPG) deg[tid] = 0;
    if (tid < NPG * NH) mxs[tid] = -1e30f;

    int off = g * CAP;
    int cnt = g_cur[g];
    if (cnt > CAP) cnt = CAP;
    for (int j = tid; j < cnt; j += 256) esh[j] = g_epack[off + j];
    if (tid < NPG) esh[cnt + tid] = (unsigned short)((tid << 5) | tid);  // self loops
    if (tid == 0) s_nE = cnt + NPG;
    __syncthreads();
    const int nE = s_nE;

    // phase 1: per-node scores + degree histogram
    if (tid < 2 * NPG * NH) {
        int t = tid;
        int which = t >= NPG * NH;
        t -= which * NPG * NH;
        int i = t >> 2, h = t & 3;
        const float* av = which ? &adsh[h * HIDC] : &ash[h * HIDC];
        float s = 0.f;
        #pragma unroll 8
        for (int k = 0; k < HIDC; k++) s += hT[(k * 21 + i) * 4 + h] * av[k];
        if (which) sdst[i][h] = s; else ssrc[i][h] = s;
    }
    for (int j = tid; j < nE; j += 256) atomicAdd(&deg[esh[j] & 31], 1);
    __syncthreads();

    // phase 2: prefix
    if (tid == 0) {
        int a = 0;
        #pragma unroll
        for (int i = 0; i < NPG; i++) { dstart[i] = a; dcur[i] = a; a += deg[i]; }
        dstart[NPG] = a;
    }
    __syncthreads();

    // phase 3: scatter + score + running max
    for (int j = tid; j < nE; j += 256) {
        unsigned short ev = esh[j];
        int dl = ev & 31, sl = ev >> 5;
        int p = atomicAdd(&dcur[dl], 1);
        srcs[p] = (unsigned short)sl;
        dst16[p] = (unsigned short)dl;
        #pragma unroll
        for (int h = 0; h < NH; h++) {
            float v = ssrc[sl][h] + sdst[dl][h];
            v = (v >= 0.f) ? v : 0.2f * v;
            alpha[p][h] = v;
            atomicMaxF(&mxs[dl * NH + h], v);
        }
    }
    __syncthreads();

    // phase 4: exp + denom (serial per (dst,head), deterministic)
    if (tid < NPG * NH) {
        int dI = tid >> 2, h = tid & 3;
        int p0 = dstart[dI], p1 = dstart[dI + 1];
        float m = mxs[tid], sum = 0.f;
        for (int p = p0; p < p1; p++) {
            float e = expf(alpha[p][h] - m);
            alpha[p][h] = e;
            sum += e;
        }
        dnm[tid] = 1.f / (sum + 1e-16f);
    }
    __syncthreads();

    // phase 5: aggregation (k channel per thread within head; 4 heads at once)
    const int k = tid & 63, dgrp = tid >> 6;
    #pragma unroll
    for (int dd = 0; dd < 5; dd++) {
        int dst = dgrp * 5 + dd;
        int p0 = dstart[dst], p1 = dstart[dst + 1];
        float a0 = 0.f, a1 = 0.f, a2 = 0.f, a3 = 0.f;
        for (int p = p0; p < p1; p++) {
            int src = srcs[p];
            float4 al = *(const float4*)&alpha[p][0];
            float4 hv = *(const float4*)&hT[(k * 21 + src) * 4];
            a0 += al.x * hv.x;
            a1 += al.y * hv.y;
            a2 += al.z * hv.z;
            a3 += al.w * hv.w;
        }
        size_t ob = (size_t)(base + dst) * D;
        float vh[4] = {a0 * dnm[dst * 4 + 0] + bsh[k],
                       a1 * dnm[dst * 4 + 1] + bsh[64 + k],
                       a2 * dnm[dst * 4 + 2] + bsh[128 + k],
                       a3 * dnm[dst * 4 + 3] + bsh[192 + k]};
        #pragma unroll
        for (int h = 0; h < NH; h++) {
            float v = vh[h];
            v = (v > 0.f) ? v : expm1f(v);
            __half hi = __float2half(v);
            g_h1hi[ob + h * 64 + k] = hi;
            g_h1lo[ob + h * 64 + k] = __float2half(v - __half2float(hi));
        }
    }
}

// ---------------- layer-2 attention at super node -> xs[G,256]; resets g_cur ----------------
__global__ __launch_bounds__(256)
void k_attn2a(const float* __restrict__ asrc, const float* __restrict__ adst,
              const float* __restrict__ bias2, float* __restrict__ xs) {
    __shared__ float hsh[NPG][D];
    __shared__ float ssrc[NPG][NH];
    __shared__ float sd19[NH];
    __shared__ float ash[NH * HIDC], adsh[NH * HIDC];
    __shared__ float b2sh[D];
    __shared__ unsigned short l19[192];
    __shared__ int s_n19;
    __shared__ float al19[192 * NH];

    const int g = blockIdx.x;
    const int tid = threadIdx.x;
    const int base = g * NPG;

    const float* hp = g_h2lin + (size_t)base * D;
    for (int i = tid; i < NPG * D / 4; i += 256)
        ((float4*)&hsh[0][0])[i] = ((const float4*)hp)[i];
    for (int i = tid; i < NH * HIDC; i += 256) { ash[i] = asrc[i]; adsh[i] = adst[i]; }
    for (int i = tid; i < D; i += 256) b2sh[i] = bias2[i];
    if (tid == 0) s_n19 = 0;
    __syncthreads();

    int off = g * CAP;
    int cnt = g_cur[g];
    if (cnt > CAP) cnt = CAP;
    for (int j = tid; j < cnt; j += 256) {
        unsigned short ev = g_epack[off + j];
        if ((ev & 31) == 19) {
            int p = atomicAdd(&s_n19, 1);
            if (p < 191) l19[p] = ev >> 5;
        }
    }
    if (tid < NPG * NH) {
        int i = tid >> 2, h = tid & 3;
        float s = 0.f;
        #pragma unroll 8
        for (int c = 0; c < HIDC; c++) s += hsh[i][h * HIDC + c] * ash[h * HIDC + c];
        ssrc[i][h] = s;
    } else if (tid < NPG * NH + NH) {
        int h = tid - NPG * NH;
        float s = 0.f;
        #pragma unroll 8
        for (int c = 0; c < HIDC; c++) s += hsh[19][h * HIDC + c] * adsh[h * HIDC + c];
        sd19[h] = s;
    }
    __syncthreads();
    if (tid == 0) {
        int m = s_n19 < 191 ? s_n19 : 191;
        l19[m] = 19;
        s_n19 = m + 1;
        g_cur[g] = 0;                  // reset for next invocation's scatter
    }
    __syncthreads();
    const int ne = s_n19;

    if (tid < NH) {
        int h = tid;
        float sd = sd19[h];
        float mx = -1e30f;
        for (int p = 0; p < ne; p++) {
            float v = ssrc[l19[p]][h] + sd;
            v = (v >= 0.f) ? v : 0.2f * v;
            al19[p * NH + h] = v;
            mx = fmaxf(mx, v);
        }
        float sum = 0.f;
        for (int p = 0; p < ne; p++) {
            float ex = expf(al19[p * NH + h] - mx);
            al19[p * NH + h] = ex;
            sum += ex;
        }
        float r = 1.f / (sum + 1e-16f);
        for (int p = 0; p < ne; p++) al19[p * NH + h] *= r;
    }
    __syncthreads();
    {
        int c = tid, h = c >> 6;
        float acc = 0.f;
        for (int p = 0; p < ne; p++)
            acc += al19[p * NH + h] * hsh[l19[p]][c];
        float v = acc + b2sh[c];
        xs[(size_t)g * D + c] = (v > 0.f) ? v : expm1f(v);
    }
}

// ---------------- MLP head: warp per graph, coalesced WhT ----------------
__global__ __launch_bounds__(256)
void k_head(const float* __restrict__ xs, const float* __restrict__ bh,
            const float* __restrict__ Wc, const float* __restrict__ bc,
            float* __restrict__ out) {
    __shared__ float xss[8][256];
    const int wid = threadIdx.x >> 5, lane = threadIdx.x & 31;
    const int g = blockIdx.x * 8 + wid;

    const float4* xr = (const float4*)(xs + (size_t)g * D);
    #pragma unroll
    for (int l = 0; l < 2; l++)
        ((float4*)xss[wid])[lane + l * 32] = xr[lane + l * 32];
    __syncwarp();

    float h0 = 0.f, h1 = 0.f;
    const int j0 = lane, j1 = 32 + lane;
    #pragma unroll 8
    for (int k = 0; k < D; k++) {
        float xv = xss[wid][k];
        h0 += xv * g_WhT[k * HIDC + j0];
        h1 += xv * g_WhT[k * HIDC + j1];
    }
    h0 += bh[j0]; h1 += bh[j1];
    h0 = (h0 > 0.f) ? h0 : 0.f;
    h1 = (h1 > 0.f) ? h1 : 0.f;
    float s = h0 * Wc[j0] + h1 * Wc[j1];
    #pragma unroll
    for (int o = 16; o; o >>= 1) s += __shfl_xor_sync(0xffffffffu, s, o);
    if (lane == 0) out[g] = s + bc[0];
}

// ---------------- launcher ----------------
extern "C" void kernel_launch(void* const* d_in, const int* in_sizes, int n_in,
                              void* d_out, int out_size) {
    const float* x   = (const float*)d_in[0];
    const int*   ei  = (const int*)d_in[1];
    const float* W1  = (const float*)d_in[3];
    const float* a1s = (const float*)d_in[4];
    const float* a1d = (const float*)d_in[5];
    const float* b1  = (const float*)d_in[6];
    const float* W2  = (const float*)d_in[7];
    const float* a2s = (const float*)d_in[8];
    const float* a2d = (const float*)d_in[9];
    const float* b2  = (const float*)d_in[10];
    const float* Wh  = (const float*)d_in[11];
    const float* bh  = (const float*)d_in[12];
    const float* Wc  = (const float*)d_in[13];
    const float* bc  = (const float*)d_in[14];
    float* out = (float*)d_out;

    void *p_h1lin, *p_h2lin, *p_xhi, *p_xlo, *p_h1hi, *p_h1lo, *p_w1h, *p_w2h;
    cudaGetSymbolAddress(&p_h1lin, g_h1lin);
    cudaGetSymbolAddress(&p_h2lin, g_h2lin);
    cudaGetSymbolAddress(&p_xhi, g_xhi);
    cudaGetSymbolAddress(&p_xlo, g_xlo);
    cudaGetSymbolAddress(&p_h1hi, g_h1hi);
    cudaGetSymbolAddress(&p_h1lo, g_h1lo);
    cudaGetSymbolAddress(&p_w1h, g_w1h);
    cudaGetSymbolAddress(&p_w2h, g_w2h);

    cudaFuncSetAttribute(k_gemm_mma<IND>, cudaFuncAttributeMaxDynamicSharedMemorySize, GEMM_SMEM);
    cudaFuncSetAttribute(k_gemm_mma<D>,   cudaFuncAttributeMaxDynamicSharedMemorySize, GEMM_SMEM);

    // idx0: scatter (g_cur zeroed by previous attn2a / static init)
    k_scatter<<<(NEDGES + 255) / 256, 256>>>(ei);
    // idx1: fused x split + W1 cvt
    k_prep1<<<(N4X + N4W1 + 255) / 256, 256>>>(x, W1);
    // idx2: gemm1
    k_gemm_mma<IND><<<dim3(NNODES / 128, 2), 256, GEMM_SMEM>>>(
        (const __half*)p_xhi, (const __half*)p_xlo, (const __half*)p_w1h, (float*)p_h1lin);
    // idx3: attn1 (profiled)
    k_attn1<<<NG, 256>>>(a1s, a1d, b1);
    // idx4: W2 cvt + Wh transpose
    k_prep2<<<(N4W2 + D * HIDC + 255) / 256, 256>>>(W2, Wh);
    // idx5: gemm2
    k_gemm_mma<D><<<dim3(NNODES / 128, 2), 256, GEMM_SMEM>>>(
        (const __half*)p_h1hi, (const __half*)p_h1lo, (const __half*)p_w2h, (float*)p_h2lin);
    // idx6: attn2 -> xs (reuses g_h1lin), resets g_cur
    k_attn2a<<<NG, 256>>>(a2s, a2d, b2, (float*)p_h1lin);
    // idx7: MLP head
    k_head<<<NG / 8, 256>>>((const float*)p_h1lin, bh, Wc, bc, out);
}